// round 13
// baseline (speedup 1.0000x reference)
#include <cuda_runtime.h>
#include <cuda_bf16.h>
#include <cstdint>

#define BATCH 4096
#define NHID  512
#define BR    32
#define NBKT  1024   // bucket key = lab>>5 ; node2 = 33+bkt, node1 = 1+(bkt>>5)

#define L0_BLOCKS 512          // 4096/8 groups, S=8
#define L1_SLOTS  544          // >= 32 + 4096/8 worst-case level-1 groups (S=8)
#define L2_SLOTS  2048         // >= 1024 + 4096/4 worst-case level-2 groups (S=4)

__device__ int   d_start[NBKT + 1];
__device__ int   d_cur[NBKT];
__device__ int   d_perm[BATCH];
__device__ int   d_g1off[33];        // prefix of level-1 group counts per node
__device__ int   d_g2off[NBKT + 1];  // prefix of level-2 group counts per bucket
__device__ float d_p[3][BATCH];      // per-level probabilities

// ---------------- tables kernel: hist + scans + task tables (NO scatter) ----------------
__global__ __launch_bounds__(1024, 1)
void tables_kernel(const int* __restrict__ labels)
{
    __shared__ int hist[NBKT];
    __shared__ int wsum[32];
    __shared__ int l1cnt[32];

    const int t    = threadIdx.x;
    const int wid  = t >> 5;
    const int lane = t & 31;

    hist[t] = 0;
    __syncthreads();
    #pragma unroll
    for (int i = 0; i < 4; i++)
        atomicAdd(&hist[labels[t + i * 1024] >> 5], 1);
    __syncthreads();

    // exclusive scan of hist (warp scan + warp-sum scan)
    const int h = hist[t];
    int v = h;
    #pragma unroll
    for (int o = 1; o < 32; o <<= 1) {
        int u = __shfl_up_sync(0xffffffffu, v, o);
        if (lane >= o) v += u;
    }
    if (lane == 31) wsum[wid] = v;
    __syncthreads();
    if (wid == 0) {
        int w = wsum[lane];
        #pragma unroll
        for (int o = 1; o < 32; o <<= 1) {
            int u = __shfl_up_sync(0xffffffffu, w, o);
            if (lane >= o) w += u;
        }
        wsum[lane] = w;
    }
    __syncthreads();
    const int excl = v + (wid > 0 ? wsum[wid - 1] : 0) - h;
    d_start[t] = excl;
    d_cur[t]   = excl;
    if (t == 0) d_start[NBKT] = BATCH;
    __syncthreads();

    // level-2 group prefix: ceil(n_bkt/4)
    int g2 = (h + 3) >> 2;
    int v2 = g2;
    #pragma unroll
    for (int o = 1; o < 32; o <<= 1) {
        int u = __shfl_up_sync(0xffffffffu, v2, o);
        if (lane >= o) v2 += u;
    }
    if (lane == 31) wsum[wid] = v2;
    __syncthreads();
    if (wid == 0) {
        int w = wsum[lane];
        #pragma unroll
        for (int o = 1; o < 32; o <<= 1) {
            int u = __shfl_up_sync(0xffffffffu, w, o);
            if (lane >= o) w += u;
        }
        wsum[lane] = w;
    }
    __syncthreads();
    const int incl2 = v2 + (wid > 0 ? wsum[wid - 1] : 0);
    d_g2off[t] = incl2 - g2;
    if (t == 1023) d_g2off[NBKT] = incl2;

    // level-1 group prefix: node w owns buckets [32w, 32w+32)
    {
        int c = hist[wid * 32 + lane];
        #pragma unroll
        for (int o = 16; o; o >>= 1) c += __shfl_xor_sync(0xffffffffu, c, o);
        if (lane == 0) l1cnt[wid] = (c + 7) >> 3;
    }
    __syncthreads();
    if (t == 0) {
        int acc = 0;
        d_g1off[0] = 0;
        #pragma unroll
        for (int g = 0; g < 32; g++) { acc += l1cnt[g]; d_g1off[g + 1] = acc; }
    }
}

// ---------------- scatter kernel: 16 blocks spread the scattered STGs ----------------
__global__ __launch_bounds__(256)
void scatter_kernel(const int* __restrict__ labels)
{
    const int i = blockIdx.x * 256 + threadIdx.x;
    const int p = atomicAdd(&d_cur[labels[i] >> 5], 1);
    d_perm[p] = i;
}

// largest k with off[k] <= i
__device__ __forceinline__ int find_bucket(const int* __restrict__ off, int n, int i)
{
    int lo = 0, hi = n;
    while (lo + 1 < hi) {
        int mid = (lo + hi) >> 1;
        if (off[mid] <= i) lo = mid; else hi = mid;
    }
    return lo;
}

// ---- shared prologue: fetch sample ids/steps and stage x -------------------------
template<int SMAX>
__device__ __forceinline__ void stage_samples(
    const float* __restrict__ x, const int* __restrict__ labels,
    float4* __restrict__ xsv, int* __restrict__ sid_sm, int* __restrict__ step_sm,
    int shift, int base, int S, bool use_perm)
{
    const int tid = threadIdx.x;
    if (tid < S) {
        const int sb = use_perm ? d_perm[base + tid] : (base + tid);
        sid_sm[tid]  = sb;
        step_sm[tid] = (labels[sb] >> shift) & 31;
    }
    __syncthreads();
    #pragma unroll
    for (int s = 0; s < SMAX; s++) {
        if (s < S) {
            const float4* xg = reinterpret_cast<const float4*>(x + (size_t)sid_sm[s] * NHID);
            xsv[s * 128 + tid] = xg[tid];
        }
    }
    __syncthreads();
}

// ---------------- FMA2 group task: SMAX samples x one node, 4-warp h-split ------------
template<int SMAX, int LVL>
__device__ __forceinline__ void process_group_fma2(
    const float* __restrict__ x, const int* __restrict__ labels,
    const float* __restrict__ W,
    float4* __restrict__ xsv, float* __restrict__ part,
    int* __restrict__ sid_sm, int* __restrict__ step_sm,
    int node, int shift, int base, int S, bool use_perm)
{
    const int tid  = threadIdx.x;
    const int warp = tid >> 5;
    const int lane = tid & 31;

    stage_samples<SMAX>(x, labels, xsv, sid_sm, step_sm, shift, base, S, use_perm);

    const float* __restrict__ Wq =
        W + (size_t)node * (NHID * BR) + (warp * 128) * BR + lane;

    const uint32_t xbase =
        (uint32_t)__cvta_generic_to_shared(xsv) + (warp * 32) * 16;

    uint64_t acc2[SMAX];
    #pragma unroll
    for (int s = 0; s < SMAX; s++) acc2[s] = 0ull;

    #pragma unroll 4
    for (int t = 0; t < 32; t++) {
        const float w0 = __ldg(Wq + (4 * t + 0) * BR);
        const float w1 = __ldg(Wq + (4 * t + 1) * BR);
        const float w2 = __ldg(Wq + (4 * t + 2) * BR);
        const float w3 = __ldg(Wq + (4 * t + 3) * BR);
        uint64_t w01, w23;
        asm("mov.b64 %0, {%1, %2};" : "=l"(w01) : "f"(w0), "f"(w1));
        asm("mov.b64 %0, {%1, %2};" : "=l"(w23) : "f"(w2), "f"(w3));
        #pragma unroll
        for (int s = 0; s < SMAX; s++) {
            uint64_t x01, x23;
            const uint32_t a = xbase + (s * 128 + t) * 16;
            asm volatile("ld.shared.v2.u64 {%0, %1}, [%2];"
                         : "=l"(x01), "=l"(x23) : "r"(a));
            asm("fma.rn.f32x2 %0, %1, %2, %0;" : "+l"(acc2[s]) : "l"(x01), "l"(w01));
            asm("fma.rn.f32x2 %0, %1, %2, %0;" : "+l"(acc2[s]) : "l"(x23), "l"(w23));
        }
    }

    #pragma unroll
    for (int s = 0; s < SMAX; s++) {
        float lo, hi;
        asm("mov.b64 {%0, %1}, %2;" : "=f"(lo), "=f"(hi) : "l"(acc2[s]));
        part[(warp * SMAX + s) * 32 + lane] = lo + hi;
    }
    __syncthreads();

    #pragma unroll
    for (int si = warp; si < SMAX; si += 4) {
        float logit = part[(0 * SMAX + si) * 32 + lane]
                    + part[(1 * SMAX + si) * 32 + lane]
                    + part[(2 * SMAX + si) * 32 + lane]
                    + part[(3 * SMAX + si) * 32 + lane];
        float m = logit;
        #pragma unroll
        for (int o = 16; o; o >>= 1) m = fmaxf(m, __shfl_xor_sync(0xffffffffu, m, o));
        const float e = __expf(logit - m);
        float ssum = e;
        #pragma unroll
        for (int o = 16; o; o >>= 1) ssum += __shfl_xor_sync(0xffffffffu, ssum, o);
        if (si < S) {
            const float es = __shfl_sync(0xffffffffu, e, step_sm[si]);
            if (lane == 0) d_p[LVL][sid_sm[si]] = es / ssum;
        }
    }
}

// ---------------- level 0 kernel: independent of the sort -> separate stream ----------
__global__ __launch_bounds__(128)
void level0_kernel(const float* __restrict__ x,
                   const int* __restrict__ labels,
                   const float* __restrict__ W)
{
    __shared__ float4 xsv[8 * 128];
    __shared__ float  part[4 * 8 * 32];
    __shared__ int    sid_sm[8];
    __shared__ int    step_sm[8];

    process_group_fma2<8, 0>(x, labels, W, xsv, part, sid_sm, step_sm,
                             /*node=*/0, /*shift=*/10, blockIdx.x * 8, 8, false);
}

// ---------------- levels 1+2 kernel: one grid (keeps block mixing) ----------------
__global__ __launch_bounds__(128)
void level12_kernel(const float* __restrict__ x,
                    const int* __restrict__ labels,
                    const float* __restrict__ W)
{
    __shared__ float4 xsv[8 * 128];
    __shared__ float  part[4 * 8 * 32];
    __shared__ int    sid_sm[8];
    __shared__ int    step_sm[8];

    const int blk = blockIdx.x;

    if (blk < L1_SLOTS) {
        const int i = blk;
        if (i >= d_g1off[32]) return;
        const int g    = find_bucket(d_g1off, 32, i);
        const int base = d_start[g * 32] + (i - d_g1off[g]) * 8;
        const int S    = min(8, d_start[g * 32 + 32] - base);
        process_group_fma2<8, 1>(x, labels, W, xsv, part, sid_sm, step_sm,
                                 1 + g, /*shift=*/5, base, S, true);
    } else {
        const int i = blk - L1_SLOTS;
        if (i >= d_g2off[NBKT]) return;
        const int k    = find_bucket(d_g2off, NBKT, i);
        const int base = d_start[k] + (i - d_g2off[k]) * 4;
        const int S    = min(4, d_start[k + 1] - base);
        process_group_fma2<4, 2>(x, labels, W, xsv, part, sid_sm, step_sm,
                                 33 + k, /*shift=*/0, base, S, true);
    }
}

__global__ __launch_bounds__(256)
void combine_kernel(float* __restrict__ out)
{
    const int b = blockIdx.x * 256 + threadIdx.x;
    out[b] = d_p[0][b] * d_p[1][b] * d_p[2][b];
}

extern "C" void kernel_launch(void* const* d_in, const int* in_sizes, int n_in,
                              void* d_out, int out_size)
{
    const float* x      = (const float*)d_in[0];   // [4096, 512] f32
    const int*   labels = (const int*)d_in[1];     // [4096] i32
    const float* W      = (const float*)d_in[2];   // [1057, 512, 32] f32
    float*       out    = (float*)d_out;           // [4096] f32

    // Host-side objects created once (no device memory involved).
    static cudaStream_t s_b = nullptr;
    static cudaEvent_t  ev_fork = nullptr, ev_join = nullptr;
    if (s_b == nullptr) {
        cudaStreamCreateWithFlags(&s_b, cudaStreamNonBlocking);
        cudaEventCreateWithFlags(&ev_fork, cudaEventDisableTiming);
        cudaEventCreateWithFlags(&ev_join, cudaEventDisableTiming);
    }

    // Fork: level0 (sort-independent) runs concurrently with tables/scatter/level12.
    cudaEventRecord(ev_fork, 0);
    cudaStreamWaitEvent(s_b, ev_fork, 0);
    level0_kernel <<<L0_BLOCKS, 128, 0, s_b>>>(x, labels, W);

    tables_kernel <<<1, 1024>>>(labels);
    scatter_kernel<<<16, 256>>>(labels);
    level12_kernel<<<L1_SLOTS + L2_SLOTS, 128>>>(x, labels, W);

    // Join, then combine.
    cudaEventRecord(ev_join, s_b);
    cudaStreamWaitEvent(0, ev_join, 0);
    combine_kernel<<<BATCH / 256, 256>>>(out);
}

// round 14
// speedup vs baseline: 1.1842x; 1.1842x over previous
#include <cuda_runtime.h>
#include <cuda_bf16.h>
#include <cstdint>

#define BATCH 4096
#define NHID  512
#define BR    32
#define NBKT  1024   // bucket key = lab>>5 ; node2 = 33+bkt, node1 = 1+(bkt>>5)

#define L0_BLOCKS 512          // 4096/8 groups, S=8
#define L1_SLOTS  544          // >= 32 + 4096/8 worst-case level-1 groups (S=8)
#define L2_SLOTS  2048         // >= 1024 + 4096/4 worst-case level-2 groups (S=4)

__device__ int   d_start[NBKT + 1];
__device__ int   d_cur[NBKT];
__device__ int   d_perm[BATCH];
__device__ int   d_g1off[33];        // prefix of level-1 group counts per node
__device__ int   d_g2off[NBKT + 1];  // prefix of level-2 group counts per bucket
__device__ float d_p[3][BATCH];      // per-level probabilities

// ---------------- tables kernel: hist + scans + task tables (NO scatter) ----------------
__global__ __launch_bounds__(1024, 1)
void tables_kernel(const int* __restrict__ labels)
{
    cudaTriggerProgrammaticLaunchCompletion();   // let scatter/levels become resident early

    __shared__ int hist[NBKT];
    __shared__ int wsum[32];
    __shared__ int l1cnt[32];

    const int t    = threadIdx.x;
    const int wid  = t >> 5;
    const int lane = t & 31;

    hist[t] = 0;
    __syncthreads();
    #pragma unroll
    for (int i = 0; i < 4; i++)
        atomicAdd(&hist[labels[t + i * 1024] >> 5], 1);
    __syncthreads();

    // exclusive scan of hist (warp scan + warp-sum scan)
    const int h = hist[t];
    int v = h;
    #pragma unroll
    for (int o = 1; o < 32; o <<= 1) {
        int u = __shfl_up_sync(0xffffffffu, v, o);
        if (lane >= o) v += u;
    }
    if (lane == 31) wsum[wid] = v;
    __syncthreads();
    if (wid == 0) {
        int w = wsum[lane];
        #pragma unroll
        for (int o = 1; o < 32; o <<= 1) {
            int u = __shfl_up_sync(0xffffffffu, w, o);
            if (lane >= o) w += u;
        }
        wsum[lane] = w;
    }
    __syncthreads();
    const int excl = v + (wid > 0 ? wsum[wid - 1] : 0) - h;
    d_start[t] = excl;
    d_cur[t]   = excl;
    if (t == 0) d_start[NBKT] = BATCH;
    __syncthreads();

    // level-2 group prefix: ceil(n_bkt/4)
    int g2 = (h + 3) >> 2;
    int v2 = g2;
    #pragma unroll
    for (int o = 1; o < 32; o <<= 1) {
        int u = __shfl_up_sync(0xffffffffu, v2, o);
        if (lane >= o) v2 += u;
    }
    if (lane == 31) wsum[wid] = v2;
    __syncthreads();
    if (wid == 0) {
        int w = wsum[lane];
        #pragma unroll
        for (int o = 1; o < 32; o <<= 1) {
            int u = __shfl_up_sync(0xffffffffu, w, o);
            if (lane >= o) w += u;
        }
        wsum[lane] = w;
    }
    __syncthreads();
    const int incl2 = v2 + (wid > 0 ? wsum[wid - 1] : 0);
    d_g2off[t] = incl2 - g2;
    if (t == 1023) d_g2off[NBKT] = incl2;

    // level-1 group prefix: node w owns buckets [32w, 32w+32)
    {
        int c = hist[wid * 32 + lane];
        #pragma unroll
        for (int o = 16; o; o >>= 1) c += __shfl_xor_sync(0xffffffffu, c, o);
        if (lane == 0) l1cnt[wid] = (c + 7) >> 3;
    }
    __syncthreads();
    if (t == 0) {
        int acc = 0;
        d_g1off[0] = 0;
        #pragma unroll
        for (int g = 0; g < 32; g++) { acc += l1cnt[g]; d_g1off[g + 1] = acc; }
    }
}

// ---------------- scatter kernel: 16 blocks spread the scattered STGs ----------------
__global__ __launch_bounds__(256)
void scatter_kernel(const int* __restrict__ labels)
{
    cudaTriggerProgrammaticLaunchCompletion();   // let levels become resident early
    cudaGridDependencySynchronize();             // wait for tables' d_cur/d_start
    const int i = blockIdx.x * 256 + threadIdx.x;
    const int p = atomicAdd(&d_cur[labels[i] >> 5], 1);
    d_perm[p] = i;
}

// largest k with off[k] <= i
__device__ __forceinline__ int find_bucket(const int* __restrict__ off, int n, int i)
{
    int lo = 0, hi = n;
    while (lo + 1 < hi) {
        int mid = (lo + hi) >> 1;
        if (off[mid] <= i) lo = mid; else hi = mid;
    }
    return lo;
}

// ---- shared prologue: fetch sample ids/steps and stage x -------------------------
template<int SMAX>
__device__ __forceinline__ void stage_samples(
    const float* __restrict__ x, const int* __restrict__ labels,
    float4* __restrict__ xsv, int* __restrict__ sid_sm, int* __restrict__ step_sm,
    int shift, int base, int S, bool use_perm)
{
    const int tid = threadIdx.x;
    if (tid < S) {
        const int sb = use_perm ? d_perm[base + tid] : (base + tid);
        sid_sm[tid]  = sb;
        step_sm[tid] = (labels[sb] >> shift) & 31;
    }
    __syncthreads();
    #pragma unroll
    for (int s = 0; s < SMAX; s++) {
        if (s < S) {
            const float4* xg = reinterpret_cast<const float4*>(x + (size_t)sid_sm[s] * NHID);
            xsv[s * 128 + tid] = xg[tid];
        }
    }
    __syncthreads();
}

// ---------------- FMA2 group task: SMAX samples x one node, 4-warp h-split ------------
template<int SMAX, int LVL>
__device__ __forceinline__ void process_group_fma2(
    const float* __restrict__ x, const int* __restrict__ labels,
    const float* __restrict__ W,
    float4* __restrict__ xsv, float* __restrict__ part,
    int* __restrict__ sid_sm, int* __restrict__ step_sm,
    int node, int shift, int base, int S, bool use_perm)
{
    const int tid  = threadIdx.x;
    const int warp = tid >> 5;
    const int lane = tid & 31;

    stage_samples<SMAX>(x, labels, xsv, sid_sm, step_sm, shift, base, S, use_perm);

    const float* __restrict__ Wq =
        W + (size_t)node * (NHID * BR) + (warp * 128) * BR + lane;

    const uint32_t xbase =
        (uint32_t)__cvta_generic_to_shared(xsv) + (warp * 32) * 16;

    uint64_t acc2[SMAX];
    #pragma unroll
    for (int s = 0; s < SMAX; s++) acc2[s] = 0ull;

    #pragma unroll 4
    for (int t = 0; t < 32; t++) {
        const float w0 = __ldg(Wq + (4 * t + 0) * BR);
        const float w1 = __ldg(Wq + (4 * t + 1) * BR);
        const float w2 = __ldg(Wq + (4 * t + 2) * BR);
        const float w3 = __ldg(Wq + (4 * t + 3) * BR);
        uint64_t w01, w23;
        asm("mov.b64 %0, {%1, %2};" : "=l"(w01) : "f"(w0), "f"(w1));
        asm("mov.b64 %0, {%1, %2};" : "=l"(w23) : "f"(w2), "f"(w3));
        #pragma unroll
        for (int s = 0; s < SMAX; s++) {
            uint64_t x01, x23;
            const uint32_t a = xbase + (s * 128 + t) * 16;
            asm volatile("ld.shared.v2.u64 {%0, %1}, [%2];"
                         : "=l"(x01), "=l"(x23) : "r"(a));
            asm("fma.rn.f32x2 %0, %1, %2, %0;" : "+l"(acc2[s]) : "l"(x01), "l"(w01));
            asm("fma.rn.f32x2 %0, %1, %2, %0;" : "+l"(acc2[s]) : "l"(x23), "l"(w23));
        }
    }

    #pragma unroll
    for (int s = 0; s < SMAX; s++) {
        float lo, hi;
        asm("mov.b64 {%0, %1}, %2;" : "=f"(lo), "=f"(hi) : "l"(acc2[s]));
        part[(warp * SMAX + s) * 32 + lane] = lo + hi;
    }
    __syncthreads();

    #pragma unroll
    for (int si = warp; si < SMAX; si += 4) {
        float logit = part[(0 * SMAX + si) * 32 + lane]
                    + part[(1 * SMAX + si) * 32 + lane]
                    + part[(2 * SMAX + si) * 32 + lane]
                    + part[(3 * SMAX + si) * 32 + lane];
        float m = logit;
        #pragma unroll
        for (int o = 16; o; o >>= 1) m = fmaxf(m, __shfl_xor_sync(0xffffffffu, m, o));
        const float e = __expf(logit - m);
        float ssum = e;
        #pragma unroll
        for (int o = 16; o; o >>= 1) ssum += __shfl_xor_sync(0xffffffffu, ssum, o);
        if (si < S) {
            const float es = __shfl_sync(0xffffffffu, e, step_sm[si]);
            if (lane == 0) d_p[LVL][sid_sm[si]] = es / ssum;
        }
    }
}

// ---------------- unified levels kernel: level-0 blocks skip the dependency sync ------
__global__ __launch_bounds__(128)
void levels_kernel(const float* __restrict__ x,
                   const int* __restrict__ labels,
                   const float* __restrict__ W)
{
    cudaTriggerProgrammaticLaunchCompletion();   // let combine become resident early

    __shared__ float4 xsv[8 * 128];        // 16 KB
    __shared__ float  part[4 * 8 * 32];    // 4 KB
    __shared__ int    sid_sm[8];
    __shared__ int    step_sm[8];

    const int blk = blockIdx.x;

    if (blk < L0_BLOCKS) {
        // Sort-independent: runs concurrently with tables+scatter (no grid sync).
        process_group_fma2<8, 0>(x, labels, W, xsv, part, sid_sm, step_sm,
                                 /*node=*/0, /*shift=*/10, blk * 8, 8, false);
    } else if (blk < L0_BLOCKS + L1_SLOTS) {
        cudaGridDependencySynchronize();         // needs d_perm / task tables
        const int i = blk - L0_BLOCKS;
        if (i >= d_g1off[32]) return;
        const int g    = find_bucket(d_g1off, 32, i);
        const int base = d_start[g * 32] + (i - d_g1off[g]) * 8;
        const int S    = min(8, d_start[g * 32 + 32] - base);
        process_group_fma2<8, 1>(x, labels, W, xsv, part, sid_sm, step_sm,
                                 1 + g, /*shift=*/5, base, S, true);
    } else {
        cudaGridDependencySynchronize();         // needs d_perm / task tables
        const int i = blk - (L0_BLOCKS + L1_SLOTS);
        if (i >= d_g2off[NBKT]) return;
        const int k    = find_bucket(d_g2off, NBKT, i);
        const int base = d_start[k] + (i - d_g2off[k]) * 4;
        const int S    = min(4, d_start[k + 1] - base);
        process_group_fma2<4, 2>(x, labels, W, xsv, part, sid_sm, step_sm,
                                 33 + k, /*shift=*/0, base, S, true);
    }
}

__global__ __launch_bounds__(256)
void combine_kernel(float* __restrict__ out)
{
    cudaGridDependencySynchronize();             // wait for all d_p writes
    const int b = blockIdx.x * 256 + threadIdx.x;
    out[b] = d_p[0][b] * d_p[1][b] * d_p[2][b];
}

// ---------------- launch with PDL chaining ----------------
template<typename... Args>
static void launch_pdl(void (*kern)(Args...), dim3 grid, dim3 block, Args... args)
{
    cudaLaunchConfig_t cfg = {};
    cfg.gridDim  = grid;
    cfg.blockDim = block;
    cfg.stream   = 0;
    cudaLaunchAttribute attr[1];
    attr[0].id = cudaLaunchAttributeProgrammaticStreamSerialization;
    attr[0].val.programmaticStreamSerializationAllowed = 1;
    cfg.attrs    = attr;
    cfg.numAttrs = 1;
    cudaLaunchKernelEx(&cfg, kern, args...);
}

extern "C" void kernel_launch(void* const* d_in, const int* in_sizes, int n_in,
                              void* d_out, int out_size)
{
    const float* x      = (const float*)d_in[0];   // [4096, 512] f32
    const int*   labels = (const int*)d_in[1];     // [4096] i32
    const float* W      = (const float*)d_in[2];   // [1057, 512, 32] f32
    float*       out    = (float*)d_out;           // [4096] f32

    tables_kernel<<<1, 1024>>>(labels);
    launch_pdl(scatter_kernel, dim3(16), dim3(256), labels);
    launch_pdl(levels_kernel, dim3(L0_BLOCKS + L1_SLOTS + L2_SLOTS), dim3(128), x, labels, W);
    launch_pdl(combine_kernel, dim3(BATCH / 256), dim3(256), out);
}